// round 5
// baseline (speedup 1.0000x reference)
#include <cuda_runtime.h>
#include <cuda_bf16.h>

#define KBINS 16

// Branchless LCQ quantize-dequantize, software-pipelined (prefetch-4) mainloop.
//
// Per element:
//   f   = min(|x| * (16/alpha), 15.9999990)   // in [0,16); f near 16 <=> high
//   bi  = (int)f                              // <= 15 guaranteed
//   y15 = fma(tab[bi].x, f, tab[bi].y)        // tab = {gx, s*beta - gx*bi}
//   q   = rint(y15)                           // round-half-even, in [0,15]
//   out = copysign(lutA[q], x)                // lutA[15] = alpha (high region)

__device__ __forceinline__ float lcq_elem(float xx, float c,
                                          const float2* __restrict__ tab,
                                          const float* __restrict__ lutA) {
    float f = fminf(fabsf(xx) * c, 15.9999990f);
    int bi = (int)f;                      // trunc
    float2 gd = tab[bi];                  // {gx, d}
    float y15 = fmaf(gd.x, f, gd.y);
    int q = (int)rintf(y15);              // in [0,15]
    return copysignf(lutA[q], xx);
}

__device__ __forceinline__ void lcq_vec4(float4& v, float c,
                                         const float2* __restrict__ tab,
                                         const float* __restrict__ lutA) {
    v.x = lcq_elem(v.x, c, tab, lutA);
    v.y = lcq_elem(v.y, c, tab, lutA);
    v.z = lcq_elem(v.z, c, tab, lutA);
    v.w = lcq_elem(v.w, c, tab, lutA);
}

__global__ void __launch_bounds__(256, 5)
lcq_kernel(const float* __restrict__ x,
           const float* __restrict__ thr,
           const float* __restrict__ theta,
           const float* __restrict__ dst,
           const int* __restrict__ qp,
           float* __restrict__ out,
           long long n) {
    __shared__ float2 s_tab[KBINS];    // {gx, s*beta - gx*bi}
    __shared__ float  s_lutA[KBINS];   // alpha * expand(q/s)
    __shared__ float  s_c;             // 16/alpha

    if (threadIdx.x == 0) {
        float th[KBINS];
        float m = theta[0];
        #pragma unroll
        for (int i = 0; i < KBINS; i++) { th[i] = theta[i]; m = fmaxf(m, th[i]); }
        float sum = 0.0f;
        #pragma unroll
        for (int i = 0; i < KBINS; i++) { th[i] = expf(th[i] - m); sum += th[i]; }
        float inv = 1.0f / sum;

        float gamma[KBINS], beta[KBINS];
        float c = 0.0f;
        #pragma unroll
        for (int i = 0; i < KBINS; i++) {
            float t = th[i] * inv;
            gamma[i] = t * (float)KBINS;
            beta[i]  = c;
            c += t;
        }

        float s = (float)qp[0];        // Qp (=15)
        float alpha = thr[0];

        #pragma unroll
        for (int i = 0; i < KBINS; i++) {
            float gx = s * gamma[i] * 0.0625f;
            s_tab[i] = make_float2(gx, fmaf(-gx, (float)i, s * beta[i]));
        }

        // expand LUT: idx = last j with beta[j] <= t
        #pragma unroll
        for (int q = 0; q < KBINS; q++) {
            float t = (float)q / s;
            int idx = 0;
            #pragma unroll
            for (int j = 0; j < KBINS; j++)
                if (beta[j] <= t) idx = j;
            s_lutA[q] = alpha * ((t - beta[idx]) / gamma[idx] + dst[idx]);
        }
        s_c = 16.0f / alpha;
    }
    __syncthreads();

    const float c = s_c;

    long long gid = (long long)blockIdx.x * blockDim.x + threadIdx.x;
    long long stride = (long long)gridDim.x * blockDim.x;
    long long n4 = n >> 2;

    const float4* __restrict__ x4 = (const float4*)x;
    float4* __restrict__ o4 = (float4*)out;

    long long i = gid;

    if (i + 3 * stride < n4) {
        // Prologue: first quad in flight.
        float4 a0 = __ldcs(&x4[i]);
        float4 a1 = __ldcs(&x4[i + stride]);
        float4 a2 = __ldcs(&x4[i + 2 * stride]);
        float4 a3 = __ldcs(&x4[i + 3 * stride]);

        // Steady state: prefetch next quad BEFORE consuming current one, so
        // 4 LDG.128 are always outstanding while computing (smooth DRAM demand).
        while (i + 7 * stride < n4) {
            long long j = i + 4 * stride;
            float4 b0 = __ldcs(&x4[j]);
            float4 b1 = __ldcs(&x4[j + stride]);
            float4 b2 = __ldcs(&x4[j + 2 * stride]);
            float4 b3 = __ldcs(&x4[j + 3 * stride]);

            lcq_vec4(a0, c, s_tab, s_lutA);  __stcs(&o4[i], a0);
            lcq_vec4(a1, c, s_tab, s_lutA);  __stcs(&o4[i + stride], a1);
            lcq_vec4(a2, c, s_tab, s_lutA);  __stcs(&o4[i + 2 * stride], a2);
            lcq_vec4(a3, c, s_tab, s_lutA);  __stcs(&o4[i + 3 * stride], a3);

            a0 = b0; a1 = b1; a2 = b2; a3 = b3;
            i = j;
        }
        // Epilogue: drain last quad.
        lcq_vec4(a0, c, s_tab, s_lutA);  __stcs(&o4[i], a0);
        lcq_vec4(a1, c, s_tab, s_lutA);  __stcs(&o4[i + stride], a1);
        lcq_vec4(a2, c, s_tab, s_lutA);  __stcs(&o4[i + 2 * stride], a2);
        lcq_vec4(a3, c, s_tab, s_lutA);  __stcs(&o4[i + 3 * stride], a3);
        i += 4 * stride;
    }
    // Remainder float4s
    for (; i < n4; i += stride) {
        float4 v = __ldcs(&x4[i]);
        lcq_vec4(v, c, s_tab, s_lutA);
        __stcs(&o4[i], v);
    }
    // Scalar tail
    for (long long j = (n4 << 2) + gid; j < n; j += stride) {
        out[j] = lcq_elem(x[j], c, s_tab, s_lutA);
    }
}

extern "C" void kernel_launch(void* const* d_in, const int* in_sizes, int n_in,
                              void* d_out, int out_size) {
    // metadata order: x, threshold, theta, dst, Qn, Qp, num_elements
    const float* x     = (const float*)d_in[0];
    const float* thr   = (const float*)d_in[1];
    const float* theta = (const float*)d_in[2];
    const float* dst   = (const float*)d_in[3];
    const int*   qp    = (const int*)d_in[5];
    float* out = (float*)d_out;

    long long n = (long long)in_sizes[0];

    const int threads = 256;
    long long n4 = (n + 3) >> 2;
    int blocks = (int)((n4 + threads - 1) / threads);
    const int max_blocks = 148 * 10;   // 2 waves at 5 CTAs/SM
    if (blocks > max_blocks) blocks = max_blocks;
    if (blocks < 1) blocks = 1;

    lcq_kernel<<<blocks, threads>>>(x, thr, theta, dst, qp, out, n);
}

// round 6
// speedup vs baseline: 1.0397x; 1.0397x over previous
#include <cuda_runtime.h>
#include <cuda_bf16.h>

#define KBINS 16
#define MAGIC 8388608.0f  // 2^23

// Branchless LCQ quantize-dequantize. Per element:
//   f   = min(|x| * (16/alpha), 15.9999990)    // in [0,16); ~16 <=> high region
//   bi  = lowbits(fadd_rd(f, 2^23)) & 15       // == floor(f), bit-exact, no F2I
//   y15 = fma(tab[bi].x, f, tab[bi].y)         // tab = {gx, s*beta - gx*bi}
//   q   = lowbits(fadd_rn(y15, 2^23)) & 15     // == rint(y15), bit-exact
//   out = copysign(lutA[q], x)                 // lutA[15] = alpha (high region)

__device__ __forceinline__ float lcq_elem(float xx, float c,
                                          const float2* __restrict__ tab,
                                          const float* __restrict__ lutA) {
    float f = fminf(fabsf(xx) * c, 15.9999990f);
    int bi = __float_as_int(__fadd_rd(f, MAGIC)) & 15;   // floor(f)
    float2 gd = tab[bi];                                 // {gx, d}
    float y15 = fmaf(gd.x, f, gd.y);
    int q = __float_as_int(__fadd_rn(y15, MAGIC)) & 15;  // rint(y15)
    return copysignf(lutA[q], xx);
}

__device__ __forceinline__ void lcq_vec4(float4& v, float c,
                                         const float2* __restrict__ tab,
                                         const float* __restrict__ lutA) {
    v.x = lcq_elem(v.x, c, tab, lutA);
    v.y = lcq_elem(v.y, c, tab, lutA);
    v.z = lcq_elem(v.z, c, tab, lutA);
    v.w = lcq_elem(v.w, c, tab, lutA);
}

__global__ void __launch_bounds__(256, 6)
lcq_kernel(const float* __restrict__ x,
           const float* __restrict__ thr,
           const float* __restrict__ theta,
           const float* __restrict__ dst,
           const int* __restrict__ qp,
           float* __restrict__ out,
           long long n) {
    __shared__ float2 s_tab[KBINS];    // {gx, s*beta - gx*bi}
    __shared__ float  s_lutA[KBINS];   // alpha * expand(q/s)
    __shared__ float  s_c;             // 16/alpha

    if (threadIdx.x == 0) {
        float th[KBINS];
        float m = theta[0];
        #pragma unroll
        for (int i = 0; i < KBINS; i++) { th[i] = theta[i]; m = fmaxf(m, th[i]); }
        float sum = 0.0f;
        #pragma unroll
        for (int i = 0; i < KBINS; i++) { th[i] = expf(th[i] - m); sum += th[i]; }
        float inv = 1.0f / sum;

        float gamma[KBINS], beta[KBINS];
        float c = 0.0f;
        #pragma unroll
        for (int i = 0; i < KBINS; i++) {
            float t = th[i] * inv;
            gamma[i] = t * (float)KBINS;
            beta[i]  = c;
            c += t;
        }

        float s = (float)qp[0];        // Qp (=15)
        float alpha = thr[0];

        #pragma unroll
        for (int i = 0; i < KBINS; i++) {
            float gx = s * gamma[i] * 0.0625f;
            s_tab[i] = make_float2(gx, fmaf(-gx, (float)i, s * beta[i]));
        }

        // expand LUT: idx = last j with beta[j] <= t
        #pragma unroll
        for (int q = 0; q < KBINS; q++) {
            float t = (float)q / s;
            int idx = 0;
            #pragma unroll
            for (int j = 0; j < KBINS; j++)
                if (beta[j] <= t) idx = j;
            s_lutA[q] = alpha * ((t - beta[idx]) / gamma[idx] + dst[idx]);
        }
        s_c = 16.0f / alpha;
    }
    __syncthreads();

    const float c = s_c;

    long long gid = (long long)blockIdx.x * blockDim.x + threadIdx.x;
    long long stride = (long long)gridDim.x * blockDim.x;
    long long n4 = n >> 2;

    const float4* __restrict__ x4 = (const float4*)x;
    float4* __restrict__ o4 = (float4*)out;

    long long i = gid;
    // 4 independent LDG.128 front-batched (MLP=4); consume/store in place
    // to keep register pressure low (R4 structure — pipelining regressed).
    for (; i + 3 * stride < n4; i += 4 * stride) {
        float4 v0 = __ldcs(&x4[i]);
        float4 v1 = __ldcs(&x4[i + stride]);
        float4 v2 = __ldcs(&x4[i + 2 * stride]);
        float4 v3 = __ldcs(&x4[i + 3 * stride]);

        lcq_vec4(v0, c, s_tab, s_lutA);  __stcs(&o4[i], v0);
        lcq_vec4(v1, c, s_tab, s_lutA);  __stcs(&o4[i + stride], v1);
        lcq_vec4(v2, c, s_tab, s_lutA);  __stcs(&o4[i + 2 * stride], v2);
        lcq_vec4(v3, c, s_tab, s_lutA);  __stcs(&o4[i + 3 * stride], v3);
    }
    // Remainder float4s
    for (; i < n4; i += stride) {
        float4 v = __ldcs(&x4[i]);
        lcq_vec4(v, c, s_tab, s_lutA);
        __stcs(&o4[i], v);
    }
    // Scalar tail
    for (long long j = (n4 << 2) + gid; j < n; j += stride) {
        out[j] = lcq_elem(x[j], c, s_tab, s_lutA);
    }
}

extern "C" void kernel_launch(void* const* d_in, const int* in_sizes, int n_in,
                              void* d_out, int out_size) {
    // metadata order: x, threshold, theta, dst, Qn, Qp, num_elements
    const float* x     = (const float*)d_in[0];
    const float* thr   = (const float*)d_in[1];
    const float* theta = (const float*)d_in[2];
    const float* dst   = (const float*)d_in[3];
    const int*   qp    = (const int*)d_in[5];
    float* out = (float*)d_out;

    long long n = (long long)in_sizes[0];

    const int threads = 256;
    long long n4 = (n + 3) >> 2;
    int blocks = (int)((n4 + threads - 1) / threads);
    const int max_blocks = 148 * 12;   // 2 waves at 6 CTAs/SM
    if (blocks > max_blocks) blocks = max_blocks;
    if (blocks < 1) blocks = 1;

    lcq_kernel<<<blocks, threads>>>(x, thr, theta, dst, qp, out, n);
}

// round 7
// speedup vs baseline: 1.0991x; 1.0572x over previous
#include <cuda_runtime.h>
#include <cuda_bf16.h>

#define KBINS 16
#define MAGIC 8388608.0f   // 2^23
#define VPT 8              // float4s per thread (full blocks)
#define TPB 256
#define TILE4 (VPT * TPB)  // 2048 float4s = 32KB per CTA

// Branchless LCQ quantize-dequantize. Per element:
//   f   = min(|x| * (16/alpha), 15.9999990)    // in [0,16); ~16 <=> high region
//   bi  = lowbits(fadd_rd(f, 2^23)) & 15       // == floor(f), bit-exact
//   y15 = fma(tab[bi].x, f, tab[bi].y)         // tab = {gx, s*beta - gx*bi}
//   q   = lowbits(fadd_rn(y15, 2^23)) & 15     // == rint(y15), bit-exact
//   out = copysign(lutA[q], x)                 // lutA[15] = alpha (high region)

__device__ __forceinline__ float lcq_elem(float xx, float c,
                                          const float2* __restrict__ tab,
                                          const float* __restrict__ lutA) {
    float f = fminf(fabsf(xx) * c, 15.9999990f);
    int bi = __float_as_int(__fadd_rd(f, MAGIC)) & 15;   // floor(f)
    float2 gd = tab[bi];                                 // {gx, d}
    float y15 = fmaf(gd.x, f, gd.y);
    int q = __float_as_int(__fadd_rn(y15, MAGIC)) & 15;  // rint(y15)
    return copysignf(lutA[q], xx);
}

__device__ __forceinline__ void lcq_vec4(float4& v, float c,
                                         const float2* __restrict__ tab,
                                         const float* __restrict__ lutA) {
    v.x = lcq_elem(v.x, c, tab, lutA);
    v.y = lcq_elem(v.y, c, tab, lutA);
    v.z = lcq_elem(v.z, c, tab, lutA);
    v.w = lcq_elem(v.w, c, tab, lutA);
}

__global__ void __launch_bounds__(TPB, 5)
lcq_kernel(const float* __restrict__ x,
           const float* __restrict__ thr,
           const float* __restrict__ theta,
           const float* __restrict__ dst,
           const int* __restrict__ qp,
           float* __restrict__ out,
           int nfull_blocks,   // blocks with a complete TILE4 tile
           int n4,             // total float4 count
           int n) {            // total element count
    __shared__ float2 s_tab[KBINS];    // {gx, s*beta - gx*bi}
    __shared__ float  s_lutA[KBINS];   // alpha * expand(q/s)
    __shared__ float  s_c;             // 16/alpha

    if (threadIdx.x == 0) {
        float th[KBINS];
        float m = theta[0];
        #pragma unroll
        for (int i = 0; i < KBINS; i++) { th[i] = theta[i]; m = fmaxf(m, th[i]); }
        float sum = 0.0f;
        #pragma unroll
        for (int i = 0; i < KBINS; i++) { th[i] = expf(th[i] - m); sum += th[i]; }
        float inv = 1.0f / sum;

        float gamma[KBINS], beta[KBINS];
        float c = 0.0f;
        #pragma unroll
        for (int i = 0; i < KBINS; i++) {
            float t = th[i] * inv;
            gamma[i] = t * (float)KBINS;
            beta[i]  = c;
            c += t;
        }

        float s = (float)qp[0];        // Qp (=15)
        float alpha = thr[0];

        #pragma unroll
        for (int i = 0; i < KBINS; i++) {
            float gx = s * gamma[i] * 0.0625f;
            s_tab[i] = make_float2(gx, fmaf(-gx, (float)i, s * beta[i]));
        }

        // expand LUT: idx = last j with beta[j] <= t
        #pragma unroll
        for (int q = 0; q < KBINS; q++) {
            float t = (float)q / s;
            int idx = 0;
            #pragma unroll
            for (int j = 0; j < KBINS; j++)
                if (beta[j] <= t) idx = j;
            s_lutA[q] = alpha * ((t - beta[idx]) / gamma[idx] + dst[idx]);
        }
        s_c = 16.0f / alpha;
    }
    __syncthreads();

    const float c = s_c;
    const float4* __restrict__ x4 = (const float4*)x;
    float4* __restrict__ o4 = (float4*)out;

    int b = blockIdx.x;
    if (b < nfull_blocks) {
        // Full tile: 8 LDG.128 front-batched (MLP=8, no loop, int indexing),
        // then compute+store each in place. Contiguous 32KB tile per CTA.
        int base = b * TILE4 + (int)threadIdx.x;
        float4 v0 = __ldcs(&x4[base]);
        float4 v1 = __ldcs(&x4[base + TPB]);
        float4 v2 = __ldcs(&x4[base + 2 * TPB]);
        float4 v3 = __ldcs(&x4[base + 3 * TPB]);
        float4 v4 = __ldcs(&x4[base + 4 * TPB]);
        float4 v5 = __ldcs(&x4[base + 5 * TPB]);
        float4 v6 = __ldcs(&x4[base + 6 * TPB]);
        float4 v7 = __ldcs(&x4[base + 7 * TPB]);

        lcq_vec4(v0, c, s_tab, s_lutA);  __stcs(&o4[base],           v0);
        lcq_vec4(v1, c, s_tab, s_lutA);  __stcs(&o4[base + TPB],     v1);
        lcq_vec4(v2, c, s_tab, s_lutA);  __stcs(&o4[base + 2 * TPB], v2);
        lcq_vec4(v3, c, s_tab, s_lutA);  __stcs(&o4[base + 3 * TPB], v3);
        lcq_vec4(v4, c, s_tab, s_lutA);  __stcs(&o4[base + 4 * TPB], v4);
        lcq_vec4(v5, c, s_tab, s_lutA);  __stcs(&o4[base + 5 * TPB], v5);
        lcq_vec4(v6, c, s_tab, s_lutA);  __stcs(&o4[base + 6 * TPB], v6);
        lcq_vec4(v7, c, s_tab, s_lutA);  __stcs(&o4[base + 7 * TPB], v7);
    } else {
        // Remainder block: guarded float4 loop + scalar tail.
        for (int i = nfull_blocks * TILE4 + (int)threadIdx.x; i < n4; i += TPB) {
            float4 v = __ldcs(&x4[i]);
            lcq_vec4(v, c, s_tab, s_lutA);
            __stcs(&o4[i], v);
        }
        for (int j = (n4 << 2) + (int)threadIdx.x; j < n; j += TPB) {
            out[j] = lcq_elem(x[j], c, s_tab, s_lutA);
        }
    }
}

extern "C" void kernel_launch(void* const* d_in, const int* in_sizes, int n_in,
                              void* d_out, int out_size) {
    // metadata order: x, threshold, theta, dst, Qn, Qp, num_elements
    const float* x     = (const float*)d_in[0];
    const float* thr   = (const float*)d_in[1];
    const float* theta = (const float*)d_in[2];
    const float* dst   = (const float*)d_in[3];
    const int*   qp    = (const int*)d_in[5];
    float* out = (float*)d_out;

    int n  = in_sizes[0];
    int n4 = n >> 2;
    int nfull_blocks = n4 / TILE4;
    int has_tail = (n4 - nfull_blocks * TILE4) != 0 || (n & 3) != 0;
    int blocks = nfull_blocks + (has_tail ? 1 : 0);
    if (blocks < 1) blocks = 1;

    lcq_kernel<<<blocks, TPB>>>(x, thr, theta, dst, qp, out,
                                nfull_blocks, n4, n);
}